// round 1
// baseline (speedup 1.0000x reference)
#include <cuda_runtime.h>
#include <cuda_bf16.h>

// Problem constants (fixed by the reference: LENGTHS[i] = 1024 + 128*i, B=16)
#define T_TOK   31744
#define PREV    768
#define DIM     256
#define NDOCS   16
#define MAXLEN  2944

// GEMM tiling
#define BM 64
#define BK 16
#define BN 256
#define TM 8
#define TN 8
#define NTHREADS 256   // (BM/TM) * (BN/TN) = 8 * 32

// offs[b] = sum_{i<b} (1024 + 128*i) = 1024*b + 64*b*(b-1)
__device__ __forceinline__ int doc_offset(int b) {
    return 1024 * b + 64 * b * (b - 1);
}

// Map token index t -> flat padded output row  (b*MAXLEN + (t - offs[b]))
__device__ __forceinline__ int out_row_for_token(int t) {
    int b = 0;
#pragma unroll
    for (int i = 1; i < NDOCS; ++i) {
        if (t >= doc_offset(i)) b = i;
    }
    return b * MAXLEN + (t - doc_offset(b));
}

// Zero only the padding rows of the [NDOCS*MAXLEN, DIM] output.
// One block per padded row; 64 threads write 256 floats as float4.
__global__ void zero_pad_kernel(float* __restrict__ out) {
    int row = blockIdx.x;                 // 0 .. NDOCS*MAXLEN-1
    int b = row / MAXLEN;
    int within = row - b * MAXLEN;
    int len = 1024 + 128 * b;
    if (within < len) return;             // valid row: GEMM kernel writes it
    float4* p = reinterpret_cast<float4*>(out + (size_t)row * DIM);
    p[threadIdx.x] = make_float4(0.f, 0.f, 0.f, 0.f);
}

// Fused GEMM + scatter:
//   out[row(t), :] = A[t, :] @ W + bias      for t in [0, T_TOK)
// A: [T_TOK, PREV] row-major, W: [PREV, DIM] row-major.
__global__ __launch_bounds__(NTHREADS)
void gemm_scatter_kernel(const float* __restrict__ A,
                         const float* __restrict__ W,
                         const float* __restrict__ bias,
                         float* __restrict__ out) {
    __shared__ float As[BK][BM];   // A tile stored k-major (transposed)
    __shared__ float Bs[BK][BN];

    const int tid = threadIdx.x;
    const int m0  = blockIdx.x * BM;

    // Thread micro-tile coordinates: 8 row-groups x 32 col-groups
    const int tm = tid >> 5;   // 0..7  -> rows tm*8 .. tm*8+7
    const int tn = tid & 31;   // 0..31 -> cols tn*8 .. tn*8+7

    float acc[TM][TN];
#pragma unroll
    for (int i = 0; i < TM; ++i)
#pragma unroll
        for (int j = 0; j < TN; ++j) acc[i][j] = 0.f;

    // A-tile load coords: 64 rows x 4 float4 per row = 256 float4, one per thread
    const int ar  = tid >> 2;        // 0..63
    const int ac4 = (tid & 3) * 4;   // 0,4,8,12

    for (int k0 = 0; k0 < PREV; k0 += BK) {
        // Load A tile (transposed into smem)
        {
            const float4 v = *reinterpret_cast<const float4*>(
                A + (size_t)(m0 + ar) * PREV + k0 + ac4);
            As[ac4 + 0][ar] = v.x;
            As[ac4 + 1][ar] = v.y;
            As[ac4 + 2][ar] = v.z;
            As[ac4 + 3][ar] = v.w;
        }
        // Load B tile: 16 rows x 256 cols = 1024 float4, 4 per thread
#pragma unroll
        for (int i = 0; i < 4; ++i) {
            int idx = tid + i * NTHREADS;   // float4 index 0..1023
            int r   = idx >> 6;             // 64 float4 per row
            int c   = (idx & 63) * 4;
            *reinterpret_cast<float4*>(&Bs[r][c]) =
                *reinterpret_cast<const float4*>(W + (size_t)(k0 + r) * DIM + c);
        }
        __syncthreads();

#pragma unroll
        for (int kk = 0; kk < BK; ++kk) {
            float a[TM], bq[TN];
#pragma unroll
            for (int i = 0; i < TM; ++i) a[i] = As[kk][tm * TM + i];
#pragma unroll
            for (int j = 0; j < TN; j += 4) {
                float4 v = *reinterpret_cast<const float4*>(&Bs[kk][tn * TN + j]);
                bq[j + 0] = v.x; bq[j + 1] = v.y; bq[j + 2] = v.z; bq[j + 3] = v.w;
            }
#pragma unroll
            for (int i = 0; i < TM; ++i)
#pragma unroll
                for (int j = 0; j < TN; ++j)
                    acc[i][j] = fmaf(a[i], bq[j], acc[i][j]);
        }
        __syncthreads();
    }

    // Bias for this thread's 8 output columns
    float bb[TN];
#pragma unroll
    for (int j = 0; j < TN; j += 4) {
        float4 v = *reinterpret_cast<const float4*>(bias + tn * TN + j);
        bb[j + 0] = v.x; bb[j + 1] = v.y; bb[j + 2] = v.z; bb[j + 3] = v.w;
    }

    // Epilogue: scatter each of the 8 rows to its padded location
#pragma unroll
    for (int i = 0; i < TM; ++i) {
        int t = m0 + tm * TM + i;             // grid covers exactly T_TOK rows
        int orow = out_row_for_token(t);
        float* o = out + (size_t)orow * DIM + tn * TN;
#pragma unroll
        for (int j = 0; j < TN; j += 4) {
            float4 v;
            v.x = acc[i][j + 0] + bb[j + 0];
            v.y = acc[i][j + 1] + bb[j + 1];
            v.z = acc[i][j + 2] + bb[j + 2];
            v.w = acc[i][j + 3] + bb[j + 3];
            *reinterpret_cast<float4*>(o + j) = v;
        }
    }
}

extern "C" void kernel_launch(void* const* d_in, const int* in_sizes, int n_in,
                              void* d_out, int out_size) {
    const float* A    = (const float*)d_in[0];  // sent_embs [T_TOK, PREV]
    const float* W    = (const float*)d_in[1];  // [PREV, DIM]
    const float* bias = (const float*)d_in[2];  // [DIM]
    float* out = (float*)d_out;                 // [NDOCS*MAXLEN, DIM]

    // Padding rows (disjoint from GEMM-written rows) — independent launches.
    zero_pad_kernel<<<NDOCS * MAXLEN, DIM / 4>>>(out);
    gemm_scatter_kernel<<<T_TOK / BM, NTHREADS>>>(A, W, bias, out);
}

// round 3
// speedup vs baseline: 2.0009x; 2.0009x over previous
#include <cuda_runtime.h>
#include <cuda_bf16.h>
#include <cstdint>

// Problem constants (fixed by the reference: LENGTHS[i] = 1024 + 128*i, B=16)
#define T_TOK   31744
#define PREV    768
#define DIM     256
#define NDOCS   16
#define MAXLEN  2944

// GEMM tiling
#define BM 64
#define BN 256
#define BK 32
#define NTHREADS 256           // 8 warps: 2 (M) x 4 (N); warp tile 32 x 64
#define KTILES (PREV / BK)     // 24

// offs[b] = sum_{i<b} (1024 + 128*i) = 1024*b + 64*b*(b-1)
__device__ __forceinline__ int doc_offset(int b) {
    return 1024 * b + 64 * b * (b - 1);
}

__device__ __forceinline__ int out_row_for_token(int t) {
    int b = 0;
#pragma unroll
    for (int i = 1; i < NDOCS; ++i) {
        if (t >= doc_offset(i)) b = i;
    }
    return b * MAXLEN + (t - doc_offset(b));
}

__device__ __forceinline__ uint32_t f32_to_tf32(float f) {
    uint32_t r;
    asm("cvt.rna.tf32.f32 %0, %1;" : "=r"(r) : "f"(f));
    return r;
}

__device__ __forceinline__ void mma_tf32(float* d, const uint32_t* a, const uint32_t* b) {
    asm volatile(
        "mma.sync.aligned.m16n8k8.row.col.f32.tf32.tf32.f32 "
        "{%0,%1,%2,%3}, {%4,%5,%6,%7}, {%8,%9}, {%0,%1,%2,%3};"
        : "+f"(d[0]), "+f"(d[1]), "+f"(d[2]), "+f"(d[3])
        : "r"(a[0]), "r"(a[1]), "r"(a[2]), "r"(a[3]), "r"(b[0]), "r"(b[1]));
}

// Zero only the padding rows of the [NDOCS*MAXLEN, DIM] output.
__global__ void zero_pad_kernel(float* __restrict__ out) {
    int row = blockIdx.x;
    int b = row / MAXLEN;
    int within = row - b * MAXLEN;
    int len = 1024 + 128 * b;
    if (within < len) return;
    float4* p = reinterpret_cast<float4*>(out + (size_t)row * DIM);
    p[threadIdx.x] = make_float4(0.f, 0.f, 0.f, 0.f);
}

// Fused TF32 tensor-core GEMM + ragged->padded scatter.
//   out[row(t), :] = A[t, :] @ W + bias
__global__ __launch_bounds__(NTHREADS)
void gemm_tc_scatter_kernel(const float* __restrict__ A,
                            const float* __restrict__ W,
                            const float* __restrict__ bias,
                            float* __restrict__ out) {
    __shared__ float As[BK][BM + 4];   // k-major, +4 pad -> <=2-way conflicts
    __shared__ float Bs[BK][BN + 4];

    const int tid    = threadIdx.x;
    const int lane   = tid & 31;
    const int warpId = tid >> 5;
    const int warpM  = warpId & 1;      // 0..1  -> 32 rows each
    const int warpN  = warpId >> 1;     // 0..3  -> 64 cols each
    const int mbase  = warpM * 32;
    const int nb     = warpN * 64;
    const int gid    = lane >> 2;       // 0..7
    const int t4     = lane & 3;        // 0..3

    const int m0 = blockIdx.x * BM;

    // ---- global-load coordinates ----
    // A: 64 rows x 32 k = 512 float4, 2 per thread (transpose into smem)
    const int am0 = tid >> 3;                 // 0..31
    const int am1 = am0 + 32;                 // 32..63
    const int ak  = (tid & 7) * 4;            // 0,4,...,28
    const float* aP0 = A + (size_t)(m0 + am0) * PREV + ak;
    const float* aP1 = A + (size_t)(m0 + am1) * PREV + ak;
    // B: 32 rows x 256 cols = 2048 float4, 8 per thread (direct copy)
    int br[8], bc[8];
#pragma unroll
    for (int i = 0; i < 8; ++i) {
        int idx = tid + i * NTHREADS;
        br[i] = idx >> 6;                     // 0..31
        bc[i] = (idx & 63) * 4;               // 0..252
    }

    float acc[2][8][4];
#pragma unroll
    for (int mi = 0; mi < 2; ++mi)
#pragma unroll
        for (int ni = 0; ni < 8; ++ni)
#pragma unroll
            for (int j = 0; j < 4; ++j) acc[mi][ni][j] = 0.f;

    // ---- prefetch tile 0 ----
    float4 pa0 = *reinterpret_cast<const float4*>(aP0);
    float4 pa1 = *reinterpret_cast<const float4*>(aP1);
    float4 pb[8];
#pragma unroll
    for (int i = 0; i < 8; ++i)
        pb[i] = *reinterpret_cast<const float4*>(W + (size_t)br[i] * DIM + bc[i]);

    for (int kt = 0; kt < KTILES; ++kt) {
        // store prefetched tile to smem
        As[ak + 0][am0] = pa0.x; As[ak + 1][am0] = pa0.y;
        As[ak + 2][am0] = pa0.z; As[ak + 3][am0] = pa0.w;
        As[ak + 0][am1] = pa1.x; As[ak + 1][am1] = pa1.y;
        As[ak + 2][am1] = pa1.z; As[ak + 3][am1] = pa1.w;
#pragma unroll
        for (int i = 0; i < 8; ++i)
            *reinterpret_cast<float4*>(&Bs[br[i]][bc[i]]) = pb[i];
        __syncthreads();

        // prefetch next tile (overlaps with MMA below)
        if (kt + 1 < KTILES) {
            const int k0n = (kt + 1) * BK;
            pa0 = *reinterpret_cast<const float4*>(aP0 + k0n);
            pa1 = *reinterpret_cast<const float4*>(aP1 + k0n);
#pragma unroll
            for (int i = 0; i < 8; ++i)
                pb[i] = *reinterpret_cast<const float4*>(
                    W + (size_t)(k0n + br[i]) * DIM + bc[i]);
        }

        // compute: 4 k-steps of 8
#pragma unroll
        for (int kk = 0; kk < 4; ++kk) {
            const int kb = kk * 8;
            uint32_t afrag[2][4];
#pragma unroll
            for (int mi = 0; mi < 2; ++mi) {
                const int r = mbase + mi * 16 + gid;
                afrag[mi][0] = f32_to_tf32(As[kb + t4    ][r    ]);
                afrag[mi][1] = f32_to_tf32(As[kb + t4    ][r + 8]);
                afrag[mi][2] = f32_to_tf32(As[kb + t4 + 4][r    ]);
                afrag[mi][3] = f32_to_tf32(As[kb + t4 + 4][r + 8]);
            }
#pragma unroll
            for (int ni = 0; ni < 8; ++ni) {
                const int n = nb + ni * 8 + gid;
                uint32_t bfrag[2];
                bfrag[0] = f32_to_tf32(Bs[kb + t4    ][n]);
                bfrag[1] = f32_to_tf32(Bs[kb + t4 + 4][n]);
                mma_tf32(acc[0][ni], afrag[0], bfrag);
                mma_tf32(acc[1][ni], afrag[1], bfrag);
            }
        }
        __syncthreads();
    }

    // ---- epilogue: bias + ragged scatter ----
    float2 bv[8];
#pragma unroll
    for (int ni = 0; ni < 8; ++ni)
        bv[ni] = *reinterpret_cast<const float2*>(bias + nb + ni * 8 + 2 * t4);

#pragma unroll
    for (int mi = 0; mi < 2; ++mi) {
        const int r0 = m0 + mbase + mi * 16 + gid;
        const int o0 = out_row_for_token(r0);
        const int o1 = out_row_for_token(r0 + 8);
        float* p0 = out + (size_t)o0 * DIM + nb + 2 * t4;
        float* p1 = out + (size_t)o1 * DIM + nb + 2 * t4;
#pragma unroll
        for (int ni = 0; ni < 8; ++ni) {
            float2 v0, v1;
            v0.x = acc[mi][ni][0] + bv[ni].x;
            v0.y = acc[mi][ni][1] + bv[ni].y;
            v1.x = acc[mi][ni][2] + bv[ni].x;
            v1.y = acc[mi][ni][3] + bv[ni].y;
            *reinterpret_cast<float2*>(p0 + ni * 8) = v0;
            *reinterpret_cast<float2*>(p1 + ni * 8) = v1;
        }
    }
}

extern "C" void kernel_launch(void* const* d_in, const int* in_sizes, int n_in,
                              void* d_out, int out_size) {
    const float* A    = (const float*)d_in[0];  // sent_embs [T_TOK, PREV]
    const float* W    = (const float*)d_in[1];  // [PREV, DIM]
    const float* bias = (const float*)d_in[2];  // [DIM]
    float* out = (float*)d_out;                 // [NDOCS*MAXLEN, DIM]

    zero_pad_kernel<<<NDOCS * MAXLEN, DIM / 4>>>(out);
    gemm_tc_scatter_kernel<<<T_TOK / BM, NTHREADS>>>(A, W, bias, out);
}

// round 4
// speedup vs baseline: 2.4336x; 1.2163x over previous
#include <cuda_runtime.h>
#include <cuda_bf16.h>
#include <cstdint>

// Problem constants (fixed by the reference: LENGTHS[i] = 1024 + 128*i, B=16)
#define T_TOK   31744
#define PREV    768
#define DIM     256
#define NDOCS   16
#define MAXLEN  2944

// GEMM tiling
#define BM 64
#define BN 256
#define BK 32
#define NTHREADS 256           // 8 warps: 2 (M) x 4 (N); warp tile 32 x 64
#define KTILES (PREV / BK)     // 24

// smem strides (banks engineered):
//  ASTR=73: odd => A-transpose STS conflict-free, A-frag LDS <=2-way
//  BSTR=264: 264%32==8 => B-frag LDS conflict-free (t4*8+gid distinct)
#define ASTR 73
#define BSTR (BN + 8)

#define GRID_GEMM (T_TOK / BM)       // 496
#define PAD_ROWS  (NDOCS * MAXLEN - T_TOK)  // 15360
#define ZBLOCKS   120                 // 128 pad rows per block
#define ROWS_PER_Z (PAD_ROWS / ZBLOCKS)     // 128

// offs[b] = sum_{i<b} (1024 + 128*i) = 1024*b + 64*b*(b-1)
__device__ __forceinline__ int doc_offset(int b) {
    return 1024 * b + 64 * b * (b - 1);
}
// cumulative pad rows before doc b: P(b) = 1920*b - 64*b*(b-1)
__device__ __forceinline__ int pad_offset(int b) {
    return 1920 * b - 64 * b * (b - 1);
}

__device__ __forceinline__ int out_row_for_token(int t) {
    int b = 0;
#pragma unroll
    for (int i = 1; i < NDOCS; ++i) {
        if (t >= doc_offset(i)) b = i;
    }
    return b * MAXLEN + (t - doc_offset(b));
}

__device__ __forceinline__ int out_row_for_pad(int p) {
    int b = 0;
#pragma unroll
    for (int i = 1; i < NDOCS; ++i) {
        if (p >= pad_offset(i)) b = i;
    }
    int len = 1024 + 128 * b;
    return b * MAXLEN + len + (p - pad_offset(b));
}

__device__ __forceinline__ uint32_t f32_to_tf32(float f) {
    uint32_t r;
    asm("cvt.rna.tf32.f32 %0, %1;" : "=r"(r) : "f"(f));
    return r;
}

__device__ __forceinline__ void mma_tf32(float* d, const uint32_t* a, const uint32_t* b) {
    asm volatile(
        "mma.sync.aligned.m16n8k8.row.col.f32.tf32.tf32.f32 "
        "{%0,%1,%2,%3}, {%4,%5,%6,%7}, {%8,%9}, {%0,%1,%2,%3};"
        : "+f"(d[0]), "+f"(d[1]), "+f"(d[2]), "+f"(d[3])
        : "r"(a[0]), "r"(a[1]), "r"(a[2]), "r"(a[3]), "r"(b[0]), "r"(b[1]));
}

// Fused: TF32 tensor-core GEMM + ragged scatter (blocks < GRID_GEMM),
//        pad-row zeroing (tail ZBLOCKS blocks).
__global__ __launch_bounds__(NTHREADS)
void gemm_tc_scatter_kernel(const float* __restrict__ A,
                            const float* __restrict__ W,
                            const float* __restrict__ bias,
                            float* __restrict__ out) {
    extern __shared__ uint32_t smem[];
    // layout: As[2][BK][ASTR], then Bs[2][BK][BSTR]
    uint32_t* AsBase = smem;                      // 2*32*73
    uint32_t* BsBase = smem + 2 * BK * ASTR;      // 2*32*264

    const int tid = threadIdx.x;
    const int bx  = blockIdx.x;

    // ---------- tail blocks: zero the padding rows ----------
    if (bx >= GRID_GEMM) {
        const int z = bx - GRID_GEMM;
        const int p0 = z * ROWS_PER_Z;
        // 128 rows * 64 float4 = 8192 float4; 256 threads -> 32 each
        for (int i = tid; i < ROWS_PER_Z * (DIM / 4); i += NTHREADS) {
            int p = p0 + (i >> 6);
            int c4 = (i & 63);
            int row = out_row_for_pad(p);
            reinterpret_cast<float4*>(out + (size_t)row * DIM)[c4] =
                make_float4(0.f, 0.f, 0.f, 0.f);
        }
        return;
    }

    // ---------- GEMM blocks ----------
    const int lane   = tid & 31;
    const int warpId = tid >> 5;
    const int warpM  = warpId & 1;      // 0..1  -> 32 rows each
    const int warpN  = warpId >> 1;     // 0..3  -> 64 cols each
    const int mbase  = warpM * 32;
    const int nb     = warpN * 64;
    const int gid    = lane >> 2;       // 0..7
    const int t4     = lane & 3;        // 0..3

    const int m0 = bx * BM;

    // global-load coords
    const int am0 = tid >> 3;                 // 0..31
    const int am1 = am0 + 32;                 // 32..63
    const int ak  = (tid & 7) * 4;            // 0,4,...,28
    const float* aP0 = A + (size_t)(m0 + am0) * PREV + ak;
    const float* aP1 = A + (size_t)(m0 + am1) * PREV + ak;
    int br[8], bc[8];
#pragma unroll
    for (int i = 0; i < 8; ++i) {
        int idx = tid + i * NTHREADS;
        br[i] = idx >> 6;
        bc[i] = (idx & 63) * 4;
    }

    float acc[2][8][4];
#pragma unroll
    for (int mi = 0; mi < 2; ++mi)
#pragma unroll
        for (int ni = 0; ni < 8; ++ni)
#pragma unroll
            for (int j = 0; j < 4; ++j) acc[mi][ni][j] = 0.f;

    // ---- load tile 0 and store (converted) into stage 0 ----
    {
        float4 a0 = *reinterpret_cast<const float4*>(aP0);
        float4 a1 = *reinterpret_cast<const float4*>(aP1);
        uint32_t* As = AsBase;
        As[(ak + 0) * ASTR + am0] = f32_to_tf32(a0.x);
        As[(ak + 1) * ASTR + am0] = f32_to_tf32(a0.y);
        As[(ak + 2) * ASTR + am0] = f32_to_tf32(a0.z);
        As[(ak + 3) * ASTR + am0] = f32_to_tf32(a0.w);
        As[(ak + 0) * ASTR + am1] = f32_to_tf32(a1.x);
        As[(ak + 1) * ASTR + am1] = f32_to_tf32(a1.y);
        As[(ak + 2) * ASTR + am1] = f32_to_tf32(a1.z);
        As[(ak + 3) * ASTR + am1] = f32_to_tf32(a1.w);
        uint32_t* Bs = BsBase;
#pragma unroll
        for (int i = 0; i < 8; ++i) {
            float4 v = *reinterpret_cast<const float4*>(W + (size_t)br[i] * DIM + bc[i]);
            uint4 u;
            u.x = f32_to_tf32(v.x); u.y = f32_to_tf32(v.y);
            u.z = f32_to_tf32(v.z); u.w = f32_to_tf32(v.w);
            *reinterpret_cast<uint4*>(&Bs[br[i] * BSTR + bc[i]]) = u;
        }
    }
    __syncthreads();

    for (int kt = 0; kt < KTILES; ++kt) {
        const int cur = kt & 1;
        const uint32_t* As = AsBase + cur * BK * ASTR;
        const uint32_t* Bs = BsBase + cur * BK * BSTR;

        // issue global loads for next tile (latency hides under MMAs)
        float4 na0, na1, nbv[8];
        const bool more = (kt + 1 < KTILES);
        if (more) {
            const int k0n = (kt + 1) * BK;
            na0 = *reinterpret_cast<const float4*>(aP0 + k0n);
            na1 = *reinterpret_cast<const float4*>(aP1 + k0n);
#pragma unroll
            for (int i = 0; i < 8; ++i)
                nbv[i] = *reinterpret_cast<const float4*>(
                    W + (size_t)(k0n + br[i]) * DIM + bc[i]);
        }

        // compute on current stage: 4 k-steps of 8
#pragma unroll
        for (int kk = 0; kk < 4; ++kk) {
            const int kb = kk * 8;
            uint32_t afrag[2][4];
#pragma unroll
            for (int mi = 0; mi < 2; ++mi) {
                const int r = mbase + mi * 16 + gid;
                afrag[mi][0] = As[(kb + t4    ) * ASTR + r    ];
                afrag[mi][1] = As[(kb + t4    ) * ASTR + r + 8];
                afrag[mi][2] = As[(kb + t4 + 4) * ASTR + r    ];
                afrag[mi][3] = As[(kb + t4 + 4) * ASTR + r + 8];
            }
#pragma unroll
            for (int ni = 0; ni < 8; ++ni) {
                const int n = nb + ni * 8 + gid;
                uint32_t bfrag[2];
                bfrag[0] = Bs[(kb + t4    ) * BSTR + n];
                bfrag[1] = Bs[(kb + t4 + 4) * BSTR + n];
                mma_tf32(acc[0][ni], afrag[0], bfrag);
                mma_tf32(acc[1][ni], afrag[1], bfrag);
            }
        }

        // store next tile into the other stage
        if (more) {
            const int nxt = cur ^ 1;
            uint32_t* Asn = AsBase + nxt * BK * ASTR;
            uint32_t* Bsn = BsBase + nxt * BK * BSTR;
            Asn[(ak + 0) * ASTR + am0] = f32_to_tf32(na0.x);
            Asn[(ak + 1) * ASTR + am0] = f32_to_tf32(na0.y);
            Asn[(ak + 2) * ASTR + am0] = f32_to_tf32(na0.z);
            Asn[(ak + 3) * ASTR + am0] = f32_to_tf32(na0.w);
            Asn[(ak + 0) * ASTR + am1] = f32_to_tf32(na1.x);
            Asn[(ak + 1) * ASTR + am1] = f32_to_tf32(na1.y);
            Asn[(ak + 2) * ASTR + am1] = f32_to_tf32(na1.z);
            Asn[(ak + 3) * ASTR + am1] = f32_to_tf32(na1.w);
#pragma unroll
            for (int i = 0; i < 8; ++i) {
                uint4 u;
                u.x = f32_to_tf32(nbv[i].x); u.y = f32_to_tf32(nbv[i].y);
                u.z = f32_to_tf32(nbv[i].z); u.w = f32_to_tf32(nbv[i].w);
                *reinterpret_cast<uint4*>(&Bsn[br[i] * BSTR + bc[i]]) = u;
            }
        }
        __syncthreads();
    }

    // ---- epilogue: bias + ragged scatter ----
    float2 bv[8];
#pragma unroll
    for (int ni = 0; ni < 8; ++ni)
        bv[ni] = *reinterpret_cast<const float2*>(bias + nb + ni * 8 + 2 * t4);

#pragma unroll
    for (int mi = 0; mi < 2; ++mi) {
        const int r0 = m0 + mbase + mi * 16 + gid;
        const int o0 = out_row_for_token(r0);
        const int o1 = out_row_for_token(r0 + 8);
        float* p0 = out + (size_t)o0 * DIM + nb + 2 * t4;
        float* p1 = out + (size_t)o1 * DIM + nb + 2 * t4;
#pragma unroll
        for (int ni = 0; ni < 8; ++ni) {
            float2 v0, v1;
            v0.x = acc[mi][ni][0] + bv[ni].x;
            v0.y = acc[mi][ni][1] + bv[ni].y;
            v1.x = acc[mi][ni][2] + bv[ni].x;
            v1.y = acc[mi][ni][3] + bv[ni].y;
            *reinterpret_cast<float2*>(p0 + ni * 8) = v0;
            *reinterpret_cast<float2*>(p1 + ni * 8) = v1;
        }
    }
}

#define SMEM_BYTES ((2 * BK * ASTR + 2 * BK * BSTR) * 4)

extern "C" void kernel_launch(void* const* d_in, const int* in_sizes, int n_in,
                              void* d_out, int out_size) {
    const float* A    = (const float*)d_in[0];  // sent_embs [T_TOK, PREV]
    const float* W    = (const float*)d_in[1];  // [PREV, DIM]
    const float* bias = (const float*)d_in[2];  // [DIM]
    float* out = (float*)d_out;                 // [NDOCS*MAXLEN, DIM]

    cudaFuncSetAttribute(gemm_tc_scatter_kernel,
                         cudaFuncAttributeMaxDynamicSharedMemorySize, SMEM_BYTES);
    gemm_tc_scatter_kernel<<<GRID_GEMM + ZBLOCKS, NTHREADS, SMEM_BYTES>>>(
        A, W, bias, out);
}

// round 7
// speedup vs baseline: 3.3971x; 1.3959x over previous
#include <cuda_runtime.h>
#include <cuda_bf16.h>
#include <cstdint>

// Problem constants (fixed by the reference: LENGTHS[i] = 1024 + 128*i, B=16)
#define T_TOK   31744
#define PREV    768
#define DIM     256
#define NDOCS   16
#define MAXLEN  2944

// GEMM tiling
#define BM 64
#define BN 256
#define BK 32
#define NTHREADS 256           // 8 warps: 2 (M) x 4 (N); warp tile 32 x 64
#define KTILES (PREV / BK)     // 24

// smem strides (u32 elements)
//  ASTR=73: odd => A-transpose STS conflict-free, A-frag LDS <=2-way
//  BSTR=264: 264%32==8 => B-frag LDS conflict-free
#define ASTR 73
#define BSTR (BN + 8)

#define A_STAGE (BK * ASTR)            // 2336 u32
#define B_STAGE (BK * BSTR)            // 8448 u32
#define SMEM_U32 (2 * A_STAGE + 2 * B_STAGE)
#define SMEM_BYTES (SMEM_U32 * 4)      // 86272 B -> 2 CTAs/SM

#define GRID_GEMM (T_TOK / BM)         // 496
#define PAD_ROWS  (NDOCS * MAXLEN - T_TOK)  // 15360
#define ZBLOCKS   120
#define ROWS_PER_Z (PAD_ROWS / ZBLOCKS)     // 128

// W pre-rounded to tf32 bit patterns, same [k][n] layout
__device__ uint32_t g_WT[PREV * DIM];

// ---------------- helpers ----------------
__device__ __forceinline__ int doc_offset(int b) { return 1024 * b + 64 * b * (b - 1); }
__device__ __forceinline__ int pad_offset(int b) { return 1920 * b - 64 * b * (b - 1); }

__device__ __forceinline__ int out_row_for_token(int t) {
    int b = 0;
#pragma unroll
    for (int i = 1; i < NDOCS; ++i) if (t >= doc_offset(i)) b = i;
    return b * MAXLEN + (t - doc_offset(b));
}
__device__ __forceinline__ int out_row_for_pad(int p) {
    int b = 0;
#pragma unroll
    for (int i = 1; i < NDOCS; ++i) if (p >= pad_offset(i)) b = i;
    return b * MAXLEN + (1024 + 128 * b) + (p - pad_offset(b));
}

__device__ __forceinline__ uint32_t f32_to_tf32(float f) {
    uint32_t r;
    asm("cvt.rna.tf32.f32 %0, %1;" : "=r"(r) : "f"(f));
    return r;
}
__device__ __forceinline__ uint32_t smem_u32_addr(const void* p) {
    uint32_t a;
    asm("{ .reg .u64 t; cvta.to.shared.u64 t, %1; cvt.u32.u64 %0, t; }" : "=r"(a) : "l"(p));
    return a;
}

__device__ __forceinline__ void mma_tf32(float* d, const uint32_t* a, const uint32_t* b) {
    asm volatile(
        "mma.sync.aligned.m16n8k8.row.col.f32.tf32.tf32.f32 "
        "{%0,%1,%2,%3}, {%4,%5,%6,%7}, {%8,%9}, {%0,%1,%2,%3};"
        : "+f"(d[0]), "+f"(d[1]), "+f"(d[2]), "+f"(d[3])
        : "r"(a[0]), "r"(a[1]), "r"(a[2]), "r"(a[3]), "r"(b[0]), "r"(b[1]));
}

#define CP_ASYNC16(dst_u32, src_ptr) \
    asm volatile("cp.async.cg.shared.global [%0], [%1], 16;" \
                 :: "r"(dst_u32), "l"(src_ptr) : "memory")
#define CP_COMMIT() asm volatile("cp.async.commit_group;" ::: "memory")
#define CP_WAIT0()  asm volatile("cp.async.wait_group 0;" ::: "memory")

// ---------------- W rounding kernel (tiny) ----------------
__global__ void round_w_kernel(const float* __restrict__ W) {
    int i = blockIdx.x * 256 + threadIdx.x;
    g_WT[i] = f32_to_tf32(W[i]);
}

// ---------------- main fused kernel ----------------
__global__ __launch_bounds__(NTHREADS, 2)
void gemm_tc_scatter_kernel(const float* __restrict__ A,
                            const float* __restrict__ bias,
                            float* __restrict__ out) {
    extern __shared__ uint32_t sm[];
    uint32_t* AsBase = sm;                    // [2][BK][ASTR]
    uint32_t* BsBase = sm + 2 * A_STAGE;      // [2][BK][BSTR]

    const int tid = threadIdx.x;
    const int bx  = blockIdx.x;

    // ---- tail blocks: zero padding rows ----
    if (bx >= GRID_GEMM) {
        const int p0 = (bx - GRID_GEMM) * ROWS_PER_Z;
        for (int i = tid; i < ROWS_PER_Z * (DIM / 4); i += NTHREADS) {
            int row = out_row_for_pad(p0 + (i >> 6));
            reinterpret_cast<float4*>(out + (size_t)row * DIM)[i & 63] =
                make_float4(0.f, 0.f, 0.f, 0.f);
        }
        return;
    }

    const int lane   = tid & 31;
    const int warpId = tid >> 5;
    const int warpM  = warpId & 1;      // 0..1  -> 32 rows each
    const int warpN  = warpId >> 1;     // 0..3  -> 64 cols each
    const int mbase  = warpM * 32;
    const int nb     = warpN * 64;
    const int gid    = lane >> 2;       // 0..7
    const int t4     = lane & 3;        // 0..3

    const int m0 = bx * BM;

    // A global-load coords (transpose into smem with cvt)
    const int am0 = tid >> 3;                 // 0..31
    const int am1 = am0 + 32;                 // 32..63
    const int ak  = (tid & 7) * 4;            // 0,4,...,28
    const float* aP0 = A + (size_t)(m0 + am0) * PREV + ak;
    const float* aP1 = A + (size_t)(m0 + am1) * PREV + ak;

    // B cp.async coords: 2048 16B-chunks, 8 per thread
    int bk8[8], bc8[8];
#pragma unroll
    for (int i = 0; i < 8; ++i) {
        int idx = tid + i * NTHREADS;
        bk8[i] = idx >> 6;                    // k row 0..31
        bc8[i] = (idx & 63) * 4;              // n col 0..252
    }
    const uint32_t bsm = smem_u32_addr(BsBase);

    float acc[2][8][4];
#pragma unroll
    for (int mi = 0; mi < 2; ++mi)
#pragma unroll
        for (int ni = 0; ni < 8; ++ni)
#pragma unroll
            for (int j = 0; j < 4; ++j) acc[mi][ni][j] = 0.f;

    // ---- prologue: A0 ldg+cvt+sts, B0 cp.async, A1 ldg ----
    {
        float4 a0 = *reinterpret_cast<const float4*>(aP0);
        float4 a1 = *reinterpret_cast<const float4*>(aP1);
        uint32_t* As = AsBase;
        As[(ak + 0) * ASTR + am0] = f32_to_tf32(a0.x);
        As[(ak + 1) * ASTR + am0] = f32_to_tf32(a0.y);
        As[(ak + 2) * ASTR + am0] = f32_to_tf32(a0.z);
        As[(ak + 3) * ASTR + am0] = f32_to_tf32(a0.w);
        As[(ak + 0) * ASTR + am1] = f32_to_tf32(a1.x);
        As[(ak + 1) * ASTR + am1] = f32_to_tf32(a1.y);
        As[(ak + 2) * ASTR + am1] = f32_to_tf32(a1.z);
        As[(ak + 3) * ASTR + am1] = f32_to_tf32(a1.w);
#pragma unroll
        for (int i = 0; i < 8; ++i)
            CP_ASYNC16(bsm + (uint32_t)(bk8[i] * BSTR + bc8[i]) * 4,
                       &g_WT[(size_t)bk8[i] * DIM + bc8[i]]);
        CP_COMMIT();
    }
    float4 pa0 = *reinterpret_cast<const float4*>(aP0 + BK);
    float4 pa1 = *reinterpret_cast<const float4*>(aP1 + BK);

    for (int kt = 0; kt < KTILES; ++kt) {
        const int cur = kt & 1;
        const int nxt = cur ^ 1;
        const bool more = (kt + 1 < KTILES);

        CP_WAIT0();          // B(kt) arrived (this thread's groups)
        __syncthreads();     // all threads' B(kt) + A(kt) STS visible; stage nxt free

        // kick off B(kt+1) copy (overlaps compute below)
        if (more) {
            const int k0n = (kt + 1) * BK;
#pragma unroll
            for (int i = 0; i < 8; ++i)
                CP_ASYNC16(bsm + (uint32_t)(nxt * B_STAGE + bk8[i] * BSTR + bc8[i]) * 4,
                           &g_WT[(size_t)(k0n + bk8[i]) * DIM + bc8[i]]);
            CP_COMMIT();
        }

        // ---- compute current stage ----
        const uint32_t* As = AsBase + cur * A_STAGE;
        const uint32_t* Bs = BsBase + cur * B_STAGE;
#pragma unroll
        for (int kk = 0; kk < 4; ++kk) {
            const int kb = kk * 8;
            uint32_t afrag[2][4];
#pragma unroll
            for (int mi = 0; mi < 2; ++mi) {
                const int r = mbase + mi * 16 + gid;
                afrag[mi][0] = As[(kb + t4    ) * ASTR + r    ];
                afrag[mi][1] = As[(kb + t4    ) * ASTR + r + 8];
                afrag[mi][2] = As[(kb + t4 + 4) * ASTR + r    ];
                afrag[mi][3] = As[(kb + t4 + 4) * ASTR + r + 8];
            }
#pragma unroll
            for (int ni = 0; ni < 8; ++ni) {
                const int n = nb + ni * 8 + gid;
                uint32_t bfrag[2];
                bfrag[0] = Bs[(kb + t4    ) * BSTR + n];
                bfrag[1] = Bs[(kb + t4 + 4) * BSTR + n];
                mma_tf32(acc[0][ni], afrag[0], bfrag);
                mma_tf32(acc[1][ni], afrag[1], bfrag);
            }
        }

        // ---- store A(kt+1) into nxt; prefetch A(kt+2) ----
        if (more) {
            uint32_t* Asn = AsBase + nxt * A_STAGE;
            Asn[(ak + 0) * ASTR + am0] = f32_to_tf32(pa0.x);
            Asn[(ak + 1) * ASTR + am0] = f32_to_tf32(pa0.y);
            Asn[(ak + 2) * ASTR + am0] = f32_to_tf32(pa0.z);
            Asn[(ak + 3) * ASTR + am0] = f32_to_tf32(pa0.w);
            Asn[(ak + 0) * ASTR + am1] = f32_to_tf32(pa1.x);
            Asn[(ak + 1) * ASTR + am1] = f32_to_tf32(pa1.y);
            Asn[(ak + 2) * ASTR + am1] = f32_to_tf32(pa1.z);
            Asn[(ak + 3) * ASTR + am1] = f32_to_tf32(pa1.w);
            if (kt + 2 < KTILES) {
                const int k0 = (kt + 2) * BK;
                pa0 = *reinterpret_cast<const float4*>(aP0 + k0);
                pa1 = *reinterpret_cast<const float4*>(aP1 + k0);
            }
        }
    }

    // ---- epilogue: bias + ragged scatter ----
    float2 bv[8];
#pragma unroll
    for (int ni = 0; ni < 8; ++ni)
        bv[ni] = *reinterpret_cast<const float2*>(bias + nb + ni * 8 + 2 * t4);

#pragma unroll
    for (int mi = 0; mi < 2; ++mi) {
        const int r0 = m0 + mbase + mi * 16 + gid;
        const int o0 = out_row_for_token(r0);
        const int o1 = out_row_for_token(r0 + 8);
        float* p0 = out + (size_t)o0 * DIM + nb + 2 * t4;
        float* p1 = out + (size_t)o1 * DIM + nb + 2 * t4;
#pragma unroll
        for (int ni = 0; ni < 8; ++ni) {
            float2 v0, v1;
            v0.x = acc[mi][ni][0] + bv[ni].x;
            v0.y = acc[mi][ni][1] + bv[ni].y;
            v1.x = acc[mi][ni][2] + bv[ni].x;
            v1.y = acc[mi][ni][3] + bv[ni].y;
            *reinterpret_cast<float2*>(p0 + ni * 8) = v0;
            *reinterpret_cast<float2*>(p1 + ni * 8) = v1;
        }
    }
}

extern "C" void kernel_launch(void* const* d_in, const int* in_sizes, int n_in,
                              void* d_out, int out_size) {
    const float* A    = (const float*)d_in[0];  // sent_embs [T_TOK, PREV]
    const float* W    = (const float*)d_in[1];  // [PREV, DIM]
    const float* bias = (const float*)d_in[2];  // [DIM]
    float* out = (float*)d_out;                 // [NDOCS*MAXLEN, DIM]

    cudaFuncSetAttribute(gemm_tc_scatter_kernel,
                         cudaFuncAttributeMaxDynamicSharedMemorySize, SMEM_BYTES);

    round_w_kernel<<<(PREV * DIM) / 256, 256>>>(W);
    gemm_tc_scatter_kernel<<<GRID_GEMM + ZBLOCKS, NTHREADS, SMEM_BYTES>>>(A, bias, out);
}